// round 16
// baseline (speedup 1.0000x reference)
#include <cuda_runtime.h>
#include <cuda_bf16.h>

#define THR 1.2f

// ---------------------------------------------------------------------------
// Device globals
// ---------------------------------------------------------------------------
__device__ unsigned g_mask[512 * 1024 * 2];          // [t*64+b][px] uint2 channel masks
__device__ float    g_part[128 * 10];                // per-block FC partials
__device__ __nv_bfloat16 g_wsp[2 * 9 * 64 * 64];     // hi region: [pos][cin][co]
__device__ __nv_bfloat16 g_wloT[64 * 576];           // [co][pos*64+cin] lo weights
__device__ float    g_marg[64];                      // per-co |lo| sum bound
__device__ uint2    g_queue[128 * 8 * 4096];         // per-warp ambiguity queues
__device__ float    g_wfcT[65536 * 12];              // [co*1024+px][12] transposed wfc

__device__ __forceinline__ unsigned smem_u32(const void* p) {
    unsigned a;
    asm("{ .reg .u64 t; cvta.to.shared.u64 t, %1; cvt.u32.u64 %0, t; }"
        : "=r"(a) : "l"(p));
    return a;
}

#define LDMX4(r, addr) \
    asm volatile("ldmatrix.sync.aligned.m8n8.x4.shared.b16 {%0,%1,%2,%3}, [%4];" \
        : "=r"((r)[0]), "=r"((r)[1]), "=r"((r)[2]), "=r"((r)[3]) : "r"(addr))
#define LDMX4T(r, addr) \
    asm volatile("ldmatrix.sync.aligned.m8n8.x4.trans.shared.b16 {%0,%1,%2,%3}, [%4];" \
        : "=r"((r)[0]), "=r"((r)[1]), "=r"((r)[2]), "=r"((r)[3]) : "r"(addr))
#define MMA16816(c, a, bb0, bb1) \
    asm volatile("mma.sync.aligned.m16n8k16.row.col.f32.bf16.bf16.f32 " \
        "{%0,%1,%2,%3}, {%4,%5,%6,%7}, {%8,%9}, {%0,%1,%2,%3};" \
        : "+f"((c)[0]), "+f"((c)[1]), "+f"((c)[2]), "+f"((c)[3]) \
        : "r"((a)[0]), "r"((a)[1]), "r"((a)[2]), "r"((a)[3]), "r"(bb0), "r"(bb1))

// packed f32x2 helpers for k1
#define PACK2(d, x)   asm("mov.b64 %0, {%1,%1};" : "=l"(d) : "f"(x))
#define PACKAB(d, a, b) asm("mov.b64 %0, {%1,%2};" : "=l"(d) : "f"(a), "f"(b))
#define FMA2(acc, w, x2) \
    asm("fma.rn.f32x2 %0, %1, %2, %0;" : "+l"(acc) : "l"(w), "l"(x2))
#define UNPACK2(lo, hi, v) \
    asm("mov.b64 {%0,%1}, %2;" : "=f"(lo), "=f"(hi) : "l"(v))

// ---------------------------------------------------------------------------
// Kernel 1: conv1 (3->64) + LIF -> channel bitmasks (unchanged)
// ---------------------------------------------------------------------------
__global__ __launch_bounds__(256) void k1_conv1(const float* __restrict__ x,
                                                const float* __restrict__ w1,
                                                const float* __restrict__ b1) {
    __shared__ float xs[3 * 34 * 36];
    __shared__ float ws[64 * 27];
    __shared__ float bs[64];

    const int tb  = blockIdx.x;
    const int tid = threadIdx.x;

    for (int i = tid; i < 64 * 27; i += 256) ws[i] = w1[i];
    if (tid < 64) bs[tid] = b1[tid];

    const float* xin = x + tb * 3 * 1024;
    for (int i = tid; i < 3 * 34 * 34; i += 256) {
        int cin = i / 1156, rem = i - cin * 1156;
        int yy = rem / 34, xx = rem - yy * 34;
        int gy = yy - 1, gx = xx - 1;
        float v = 0.f;
        if (gy >= 0 && gy < 32 && gx >= 0 && gx < 32)
            v = xin[cin * 1024 + gy * 32 + gx];
        xs[cin * 1224 + yy * 36 + xx] = v;
    }
    __syncthreads();

    const int wid  = tid >> 5;
    const int lane = tid & 31;

    unsigned long long wp[27];
#pragma unroll
    for (int k = 0; k < 27; k++)
        PACKAB(wp[k], ws[lane * 27 + k], ws[(lane + 32) * 27 + k]);
    unsigned long long bias2;
    PACKAB(bias2, bs[lane], bs[lane + 32]);

    for (int seg = wid; seg < 128; seg += 8) {
        const int y   = seg >> 2;
        const int xc0 = (seg & 3) * 8;

        unsigned long long acc2[8];
#pragma unroll
        for (int px = 0; px < 8; px++) acc2[px] = bias2;

#pragma unroll
        for (int cin = 0; cin < 3; cin++) {
            const float* base = xs + cin * 1224 + xc0;
#pragma unroll
            for (int dr = 0; dr < 3; dr++) {
                const float4* rp = (const float4*)(base + (y + dr) * 36);
                float4 f0 = rp[0], f1 = rp[1], f2 = rp[2];
                unsigned long long x2[10];
                PACK2(x2[0], f0.x); PACK2(x2[1], f0.y); PACK2(x2[2], f0.z); PACK2(x2[3], f0.w);
                PACK2(x2[4], f1.x); PACK2(x2[5], f1.y); PACK2(x2[6], f1.z); PACK2(x2[7], f1.w);
                PACK2(x2[8], f2.x); PACK2(x2[9], f2.y);
                const int wb = cin * 9 + dr * 3;
#pragma unroll
                for (int px = 0; px < 8; px++) {
                    FMA2(acc2[px], wp[wb],     x2[px]);
                    FMA2(acc2[px], wp[wb + 1], x2[px + 1]);
                    FMA2(acc2[px], wp[wb + 2], x2[px + 2]);
                }
            }
        }

#pragma unroll
        for (int px = 0; px < 8; px++) {
            float lo, hi;
            UNPACK2(lo, hi, acc2[px]);
            unsigned mlo = __ballot_sync(0xffffffffu, lo >= THR);
            unsigned mhi = __ballot_sync(0xffffffffu, hi >= THR);
            if (lane == 0)
                ((uint2*)g_mask)[tb * 1024 + seg * 8 + px] = make_uint2(mlo, mhi);
        }
    }
}

// ---------------------------------------------------------------------------
// Kernel 2a: split w2 -> bf16 hi (MMA layout) + bf16 lo (coalesced [co][...])
// ---------------------------------------------------------------------------
__global__ void k2a_split(const float* __restrict__ w2) {
    int i = blockIdx.x * 256 + threadIdx.x;
    if (i >= 36864) return;
    int co = i / 576, rest = i - co * 576;
    int cin = rest / 9, pos = rest - cin * 9;
    float w = w2[i];
    __nv_bfloat16 hi = __float2bfloat16(w);
    __nv_bfloat16 lo = __float2bfloat16(w - __bfloat162float(hi));
    g_wsp[pos * 4096 + cin * 64 + co] = hi;
    g_wloT[co * 576 + pos * 64 + cin] = lo;
}

// ---------------------------------------------------------------------------
// Kernel 2c: per-co margin = sum |lo| (safe upper bound on |S_lo|)
// ---------------------------------------------------------------------------
__global__ void k2c_margin() {
    int co = threadIdx.x;
    if (co < 64) {
        float m = 0.f;
        for (int j = 0; j < 576; j++)
            m += fabsf(__bfloat162float(g_wloT[co * 576 + j]));
        g_marg[co] = m * 1.0001f + 1e-5f;
    }
}

// ---------------------------------------------------------------------------
// Kernel 2b: transpose wfc -> [co*1024+px][12]
// ---------------------------------------------------------------------------
__global__ void k2b_transpose(const float* __restrict__ wfc) {
    int i = blockIdx.x * 256 + threadIdx.x;   // 0..65535
    float v[10];
#pragma unroll
    for (int o = 0; o < 10; o++) v[o] = wfc[o * 65536 + i];
    float4* dst = (float4*)(g_wfcT + i * 12);
    dst[0] = make_float4(v[0], v[1], v[2], v[3]);
    dst[1] = make_float4(v[4], v[5], v[6], v[7]);
    dst[2] = make_float4(v[8], v[9], 0.f, 0.f);
}

// ---------------------------------------------------------------------------
// Kernel 2: conv2 via SINGLE hi-bf16 mma.sync pass + margin-gated exact
// lo-corrections + LIF + count over t + fused FC.
// Grid: (2 strips of 16 rows, 64 b) = 128 CTAs, 256 threads = 8 warps.
// Warp = 2 rows = 4 m16 tiles (R12 structure), half the MMAs of R12.
// SMEM: thr2[64] @0 | marg[64] @256 | red @512 | qcnt[8] @896 | LUT @1024
//       B(hi) @5120: 9 x 8KB (73728B) | plane @78848: 612 x 128B (78336B)
// ---------------------------------------------------------------------------
#define OFF_MARG  256
#define OFF_RED   512
#define OFF_QCNT  896
#define OFF_LUT   1024
#define OFF_B     5120
#define OFF_PLANE 78848
#define SMEM_K2   157184

__global__ __launch_bounds__(256, 1) void k2_mma(const float* __restrict__ b2) {
    extern __shared__ __align__(128) char sm[];
    const unsigned smb = smem_u32(sm);

    const int sy  = blockIdx.x;       // 16-row strip (0..1)
    const int b   = blockIdx.y;
    const int tid = threadIdx.x;
    const int wid = tid >> 5;
    const int lane = tid & 31;
    const int ry2 = wid * 2;          // first image row of this warp (0..14)

    // LUT: byte -> 8 bf16 (0/1)
    if (tid < 256) {
        int v = tid;
        unsigned w[4];
#pragma unroll
        for (int i = 0; i < 4; i++) {
            unsigned lo = ((v >> (2 * i)) & 1)     ? 0x3F80u : 0u;
            unsigned hi = ((v >> (2 * i + 1)) & 1) ? 0x3F800000u : 0u;
            w[i] = lo | hi;
        }
        *(uint4*)(sm + OFF_LUT + v * 16) = make_uint4(w[0], w[1], w[2], w[3]);
    }
    if (tid < 64) {
        ((float*)sm)[tid] = THR - b2[tid];
        ((float*)(sm + OFF_MARG))[tid] = g_marg[tid];
    }
    if (tid < 8) ((unsigned*)(sm + OFF_QCNT))[tid] = 0u;

    // hi weights -> SMEM with chunk swizzle j ^= (row&7)  (9 tables x 8KB)
    {
        const char* src = (const char*)g_wsp;
        for (int i = tid; i < 4608; i += 256) {
            int off = i * 16;
            int inner = off & 8191;
            int r = inner >> 7, j = (inner >> 4) & 7;
            uint4 v = *(const uint4*)(src + off);
            *(uint4*)(sm + OFF_B + (off & ~8191) + (r << 7) + ((j ^ (r & 7)) << 4)) = v;
        }
    }
    __syncthreads();

    const float* s_thr2 = (const float*)sm;
    const float* s_marg = (const float*)(sm + OFF_MARG);
    unsigned* s_qcnt = (unsigned*)(sm + OFF_QCNT);
    const unsigned qbase = ((unsigned)(blockIdx.y * 2 + blockIdx.x) * 8 + wid) * 4096;

    // nibble-packed spike counters: cntp[tile][q], nf in nibbles (cnt<=8)
    unsigned cntp[4][4];
#pragma unroll
    for (int h = 0; h < 4; h++)
#pragma unroll
        for (int q = 0; q < 4; q++) cntp[h][q] = 0u;

    const uint2* gm = (const uint2*)g_mask;
    const unsigned p0 = smb + OFF_PLANE;

    for (int t = 0; t < 8; t++) {
        // --- expand spike masks for this t: 612 rows (18 image rows + x halo)
        for (int r = tid; r < 612; r += 256) {
            int iy = r / 34, ixp = r - iy * 34;
            int y = sy * 16 - 1 + iy;
            int ix = ixp - 1;
            uint2 m = make_uint2(0u, 0u);
            if ((unsigned)y < 32u && (unsigned)ix < 32u)
                m = gm[(t * 64 + b) * 1024 + y * 32 + ix];
            char* pb = sm + OFF_PLANE + r * 128;
            const int rs = r & 7;
#pragma unroll
            for (int k = 0; k < 4; k++) {
                unsigned byte = (m.x >> (8 * k)) & 0xFFu;
                uint4 v = *(const uint4*)(sm + OFF_LUT + byte * 16);
                *(uint4*)(pb + ((k ^ rs) << 4)) = v;
            }
#pragma unroll
            for (int k = 4; k < 8; k++) {
                unsigned byte = (m.y >> (8 * (k - 4))) & 0xFFu;
                uint4 v = *(const uint4*)(sm + OFF_LUT + byte * 16);
                *(uint4*)(pb + ((k ^ rs) << 4)) = v;
            }
        }
        __syncthreads();

        float c[4][8][4];   // [tile][nf][q] fp32 accumulators (hi pass only)
#pragma unroll
        for (int h = 0; h < 4; h++)
#pragma unroll
            for (int nf = 0; nf < 8; nf++)
#pragma unroll
                for (int q = 0; q < 4; q++) c[h][nf][q] = 0.f;

#pragma unroll 1
        for (int pos = 0; pos < 9; pos++) {
            const int dy = pos / 3, dx = pos - dy * 3;
            const int prbase = (ry2 + dy) * 34 + dx + (lane & 15);
#pragma unroll 1
            for (int kt = 0; kt < 4; kt++) {
                const unsigned kcol = (unsigned)(kt * 2 + (lane >> 4));
                unsigned a[4][4];
#pragma unroll
                for (int h = 0; h < 4; h++) {
                    const int prb = prbase + (h >> 1) * 34 + (h & 1) * 16;
                    LDMX4(a[h], p0 + prb * 128 + ((kcol ^ (prb & 7)) << 4));
                }
                const int brow = kt * 16 + (lane & 15);
                const unsigned bjb = (unsigned)(lane >> 4);
                const unsigned wb = smb + OFF_B + pos * 8192 + brow * 128;
#pragma unroll
                for (int nt = 0; nt < 4; nt++) {
                    unsigned bb[4];
                    LDMX4T(bb, wb + (((nt * 2 + bjb) ^ (brow & 7)) << 4));
#pragma unroll
                    for (int h = 0; h < 4; h++) {
                        MMA16816(c[h][nt * 2],     a[h], bb[0], bb[1]);
                        MMA16816(c[h][nt * 2 + 1], a[h], bb[2], bb[3]);
                    }
                }
            }
        }

        // --- threshold with margin gate; ambiguous -> per-warp queue
#pragma unroll
        for (int hh = 0; hh < 4; hh++)
#pragma unroll
            for (int nf = 0; nf < 8; nf++)
#pragma unroll
                for (int qq = 0; qq < 4; qq++) {
                    const int co = nf * 8 + (lane & 3) * 2 + (qq & 1);
                    const float d = c[hh][nf][qq] - s_thr2[co];
                    cntp[hh][qq] += (d >= 0.f) ? (1u << (4 * nf)) : 0u;
                    if (fabsf(d) < s_marg[co]) {
                        unsigned p = atomicAdd(&s_qcnt[wid], 1u);
                        g_queue[qbase + p] = make_uint2(
                            (unsigned)lane | ((unsigned)hh << 5) |
                            ((unsigned)nf << 7) | ((unsigned)qq << 10),
                            __float_as_uint(d));
                    }
                }

        // --- exact lo-corrections (warp-cooperative, plane still resident)
        __syncwarp();
        __threadfence_block();
        {
            const unsigned n = s_qcnt[wid];
            for (unsigned e = 0; e < n; e++) {
                uint2 ent = g_queue[qbase + e];
                const unsigned code = ent.x;
                const float d = __uint_as_float(ent.y);
                const int ls = code & 31;
                const int hh = (code >> 5) & 3;
                const int nf = (code >> 7) & 7;
                const int qq = (code >> 10) & 3;
                const int co = nf * 8 + (ls & 3) * 2 + (qq & 1);
                const int xcol = (hh & 1) * 16 + (ls >> 2) + ((qq >> 1) << 3);
                const int Lr = ry2 + (hh >> 1);
                float part = 0.f;
#pragma unroll
                for (int it = 0; it < 18; it++) {
                    const int i = lane + it * 32;
                    const int pos = i >> 6;
                    const int cin = i & 63;
                    const int dy = pos / 3, dx = pos - dy * 3;
                    const int pr = (Lr + dy) * 34 + xcol + dx;
                    const int j0 = cin >> 3;
                    float sp = __bfloat162float(*(const __nv_bfloat16*)(
                        sm + OFF_PLANE + pr * 128 + ((j0 ^ (pr & 7)) << 4) +
                        (cin & 7) * 2));
                    float wl = __bfloat162float(g_wloT[co * 576 + i]);
                    part += sp * wl;
                }
                part += __shfl_down_sync(0xffffffffu, part, 16);
                part += __shfl_down_sync(0xffffffffu, part, 8);
                part += __shfl_down_sync(0xffffffffu, part, 4);
                part += __shfl_down_sync(0xffffffffu, part, 2);
                part += __shfl_down_sync(0xffffffffu, part, 1);
                const float S = __shfl_sync(0xffffffffu, part, 0);
                if (lane == ls) {
                    const bool newsp = (d + S) >= 0.f;
                    const bool oldsp = (d >= 0.f);
                    if (newsp != oldsp) {
                        const int delta = newsp ? (1 << (4 * nf)) : -(1 << (4 * nf));
                        switch ((hh << 2) | qq) {
                            case 0:  cntp[0][0] += delta; break;
                            case 1:  cntp[0][1] += delta; break;
                            case 2:  cntp[0][2] += delta; break;
                            case 3:  cntp[0][3] += delta; break;
                            case 4:  cntp[1][0] += delta; break;
                            case 5:  cntp[1][1] += delta; break;
                            case 6:  cntp[1][2] += delta; break;
                            case 7:  cntp[1][3] += delta; break;
                            case 8:  cntp[2][0] += delta; break;
                            case 9:  cntp[2][1] += delta; break;
                            case 10: cntp[2][2] += delta; break;
                            case 11: cntp[2][3] += delta; break;
                            case 12: cntp[3][0] += delta; break;
                            case 13: cntp[3][1] += delta; break;
                            case 14: cntp[3][2] += delta; break;
                            default: cntp[3][3] += delta; break;
                        }
                    }
                }
            }
            if (lane == 0) s_qcnt[wid] = 0u;
            __syncwarp();
        }

        __syncthreads();   // plane reads done before next t overwrites it
    }

    // --- fused FC fold
    float oa[10];
#pragma unroll
    for (int o = 0; o < 10; o++) oa[o] = 0.f;
#pragma unroll
    for (int h = 0; h < 4; h++) {
        const int gpbase = (sy * 16 + ry2 + (h >> 1)) * 32 + (h & 1) * 16;
#pragma unroll
        for (int q = 0; q < 4; q++) {
            const int gp = gpbase + (lane >> 2) + ((q >> 1) << 3);
#pragma unroll
            for (int nf = 0; nf < 8; nf++) {
                const int co = nf * 8 + (lane & 3) * 2 + (q & 1);
                const float4* p = (const float4*)(g_wfcT + (co * 1024 + gp) * 12);
                float4 f0 = p[0], f1 = p[1], f2 = p[2];
                const float cc = (float)((cntp[h][q] >> (4 * nf)) & 0xFu);
                oa[0] += cc * f0.x; oa[1] += cc * f0.y; oa[2] += cc * f0.z; oa[3] += cc * f0.w;
                oa[4] += cc * f1.x; oa[5] += cc * f1.y; oa[6] += cc * f1.z; oa[7] += cc * f1.w;
                oa[8] += cc * f2.x; oa[9] += cc * f2.y;
            }
        }
    }

    float* red = (float*)(sm + OFF_RED);
#pragma unroll
    for (int o = 0; o < 10; o++) {
        float v = oa[o];
        v += __shfl_down_sync(0xffffffffu, v, 16);
        v += __shfl_down_sync(0xffffffffu, v, 8);
        v += __shfl_down_sync(0xffffffffu, v, 4);
        v += __shfl_down_sync(0xffffffffu, v, 2);
        v += __shfl_down_sync(0xffffffffu, v, 1);
        if (lane == 0) red[wid * 10 + o] = v;
    }
    __syncthreads();
    if (tid < 10) {
        float s = 0.f;
#pragma unroll
        for (int w = 0; w < 8; w++) s += red[w * 10 + tid];
        g_part[(b * 2 + sy) * 10 + tid] = s;
    }
}

// ---------------------------------------------------------------------------
// Kernel 3: final reduction
// ---------------------------------------------------------------------------
__global__ void k3_final(const float* __restrict__ bfc, float* __restrict__ out) {
    const int tid = threadIdx.x;
    if (tid < 640) {
        const int b = tid / 10, o = tid - b * 10;
        float s = 8.f * bfc[o];
#pragma unroll
        for (int k = 0; k < 2; k++) s += g_part[(b * 2 + k) * 10 + o];
        out[tid] = s;
    }
}

extern "C" void kernel_launch(void* const* d_in, const int* in_sizes, int n_in,
                              void* d_out, int out_size) {
    const float* x   = (const float*)d_in[0];  // [8,64,3,32,32]
    const float* w1  = (const float*)d_in[1];  // [64,3,3,3]
    const float* b1  = (const float*)d_in[2];  // [64]
    const float* w2  = (const float*)d_in[3];  // [64,64,3,3]
    const float* b2  = (const float*)d_in[4];  // [64]
    const float* wfc = (const float*)d_in[5];  // [10, 65536]
    const float* bfc = (const float*)d_in[6];  // [10]
    float* out = (float*)d_out;                // [64,10]

    cudaFuncSetAttribute(k2_mma, cudaFuncAttributeMaxDynamicSharedMemorySize,
                         SMEM_K2);

    k1_conv1<<<512, 256>>>(x, w1, b1);
    k2a_split<<<144, 256>>>(w2);
    k2c_margin<<<1, 64>>>();
    k2b_transpose<<<256, 256>>>(wfc);
    k2_mma<<<dim3(2, 64), 256, SMEM_K2>>>(b2);
    k3_final<<<1, 640>>>(bfc, out);
}